// round 9
// baseline (speedup 1.0000x reference)
#include <cuda_runtime.h>
#include <math.h>
#include <stdint.h>

#define KTAGS 64
#define DDIM  128
#define VWORDS 50000
#define NV   (VWORDS + 2)
#define BATCHN 2048
#define TLEN 256
#define BOS_TAG 63
#define EOS_TAG 62
#define TINYV 1e-45f
#define ASTR  68
#define SCL   0.015625f   // 1/64 folded scaling

typedef unsigned long long u64;

__device__ __forceinline__ u64 pack2(float lo, float hi) {
    u64 r; asm("mov.b64 %0,{%1,%2};" : "=l"(r) : "f"(lo), "f"(hi)); return r;
}
__device__ __forceinline__ u64 fma2(u64 a, u64 b, u64 c) {
    u64 d; asm("fma.rn.f32x2 %0,%1,%2,%3;" : "=l"(d) : "l"(a), "l"(b), "l"(c)); return d;
}
__device__ __forceinline__ float2 unpack2(u64 v) {
    float2 f; asm("mov.b64 {%0,%1},%2;" : "=f"(f.x), "=f"(f.y) : "l"(v)); return f;
}
// pack two fp32 -> bf16x2 (first arg = hi half)
__device__ __forceinline__ uint32_t cvt_bf16x2(float hi, float lo) {
    uint32_t r; asm("cvt.rn.bf16x2.f32 %0, %1, %2;" : "=r"(r) : "f"(hi), "f"(lo)); return r;
}
// D(16x8,f32) += A(16x16,bf16) @ B(16x8,bf16)
__device__ __forceinline__ void mma16816(float& d0, float& d1, float& d2, float& d3,
        uint32_t a0, uint32_t a1, uint32_t a2, uint32_t a3,
        uint32_t b0, uint32_t b1) {
    asm("mma.sync.aligned.m16n8k16.row.col.f32.bf16.bf16.f32 "
        "{%0,%1,%2,%3}, {%4,%5,%6,%7}, {%8,%9}, {%0,%1,%2,%3};"
        : "+f"(d0), "+f"(d1), "+f"(d2), "+f"(d3)
        : "r"(a0), "r"(a1), "r"(a2), "r"(a3), "r"(b0), "r"(b1));
}

// Scratch (static device global; no dynamic allocation)
__device__ float g_Bt[(size_t)NV * KTAGS];   // emission table, word-major [w][k]

// ---------------------------------------------------------------------------
// Kernel 1: emission table g_Bt[w][k] = exp(dot(ThetaB[k,:], E[w,:]))
// ---------------------------------------------------------------------------
__global__ __launch_bounds__(256) void emit_table_kernel(
        const float* __restrict__ ThetaB, const float* __restrict__ E) {
    __shared__ __align__(16) float sE[64 * 65];
    __shared__ __align__(16) float sTh[64 * ASTR];

    int tid = threadIdx.x;
    int wq  = tid & 15;
    int kq  = tid >> 4;
    int w0  = blockIdx.x * 64;

    u64 acc[4][2];
#pragma unroll
    for (int a = 0; a < 4; a++) { acc[a][0] = 0ull; acc[a][1] = 0ull; }

    for (int dc = 0; dc < 2; dc++) {
        for (int idx = tid; idx < 64 * 64; idx += 256) {
            int k = idx >> 6, dl = idx & 63;
            sTh[dl * ASTR + k] = ThetaB[k * DDIM + dc * 64 + dl];
        }
        for (int idx = tid; idx < 64 * 64; idx += 256) {
            int w = idx >> 6, dl = idx & 63;
            int wg = w0 + w;
            sE[w * 65 + dl] = (wg < NV) ? E[(size_t)wg * DDIM + dc * 64 + dl] : 0.0f;
        }
        __syncthreads();

#pragma unroll 8
        for (int dl = 0; dl < 64; dl++) {
            ulonglong2 th = *(const ulonglong2*)&sTh[dl * ASTR + kq * 4];
#pragma unroll
            for (int ww = 0; ww < 4; ww++) {
                float e = sE[(wq * 4 + ww) * 65 + dl];
                u64 ep = pack2(e, e);
                acc[ww][0] = fma2(ep, th.x, acc[ww][0]);
                acc[ww][1] = fma2(ep, th.y, acc[ww][1]);
            }
        }
        __syncthreads();
    }

#pragma unroll
    for (int ww = 0; ww < 4; ww++) {
        int w = w0 + wq * 4 + ww;
        if (w < NV) {
            float2 p0 = unpack2(acc[ww][0]);
            float2 p1 = unpack2(acc[ww][1]);
            float4 r;
            r.x = expf(p0.x); r.y = expf(p0.y);
            r.z = expf(p1.x); r.w = expf(p1.y);
            if (kq == 15) { r.z = TINYV; r.w = TINYV; }
            *(float4*)&g_Bt[(size_t)w * KTAGS + kq * 4] = r;
        }
    }
}

// ---------------------------------------------------------------------------
// Kernel 2: forward scan via mma.sync m16n8k16 bf16, N-SPLIT across 8 warps.
// CTA = 256 threads = 8 warps, 16 sentences. Warp w owns output tags
// 8w..8w+7 (one nb block): 4 MMAs/step = 2 independent chains of depth 2.
// Exchange: thread publishes uint2 (row g / row g+8 bf16x2) with one STS.64;
// Af[kc] = one LDS.128 from the interleaved halves of warps 2kc, 2kc+1.
// lane: g = lane>>2 (sentence, +8 for second), q = lane&3.
// ---------------------------------------------------------------------------
__global__ __launch_bounds__(256, 1) void crf_scan_kernel(
        const float* __restrict__ WA,
        const int* __restrict__ words, float* __restrict__ out) {
    __shared__ __align__(16) float sWA[KTAGS * KTAGS];   // 16 KB
    __shared__ int sWT[TLEN][16];                         // 16 KB
    __shared__ __align__(16) uint2 sX[2][4][32][2];       // [p][kc][lane][half], 4 KB
    __shared__ float sZ[8][16];

    int tid  = threadIdx.x;
    int w    = tid >> 5;      // warp 0..7 = nb block
    int lane = tid & 31;
    int g    = lane >> 2;     // 0..7
    int q    = lane & 3;      // 0..3
    int s0   = blockIdx.x * 16;

    for (int idx = tid; idx < KTAGS * KTAGS / 4; idx += 256)
        ((float4*)sWA)[idx] = ((const float4*)WA)[idx];
    for (int idx = tid; idx < 16 * TLEN; idx += 256) {
        int s = idx >> 8, tt = idx & (TLEN - 1);
        sWT[tt][s] = words[(size_t)(s0 + s) * TLEN + tt];
    }
    __syncthreads();

    // B fragments for own nb = w (col n = 8w + g)
    uint32_t Bf[4][2];
    {
        int n = 8 * w + g;
        bool bos = (n == BOS_TAG);
#pragma unroll
        for (int kc = 0; kc < 4; kc++) {
            int k0 = 16 * kc + 2 * q;
            float v0 = bos ? 0.0f : expf(sWA[(k0)     * KTAGS + n]) * SCL;
            float v1 = bos ? 0.0f : expf(sWA[(k0 + 1) * KTAGS + n]) * SCL;
            float v8 = bos ? 0.0f : expf(sWA[(k0 + 8) * KTAGS + n]) * SCL;
            float v9 = bos ? 0.0f : expf(sWA[(k0 + 9) * KTAGS + n]) * SCL;
            Bf[kc][0] = cvt_bf16x2(v1, v0);
            Bf[kc][1] = cvt_bf16x2(v9, v8);
        }
    }

    int n0 = 8 * w + 2 * q;   // this thread's even tag
    // EOS column entries for this thread's 2 tags
    float eos0 = expf(sWA[(n0)     * KTAGS + EOS_TAG]) * SCL;
    float eos1 = expf(sWA[(n0 + 1) * KTAGS + EOS_TAG]) * SCL;

    // alpha_1[s][n] = A'[BOS][n] * emis(pos 1)[n]  (fp32)
    float d0, d1, d2, d3;
    {
        float rb0 = (n0     == BOS_TAG) ? 0.0f : expf(sWA[BOS_TAG * KTAGS + n0])     * SCL;
        float rb1 = (n0 + 1 == BOS_TAG) ? 0.0f : expf(sWA[BOS_TAG * KTAGS + n0 + 1]) * SCL;
        int w1g  = sWT[1][g];
        int w1g8 = sWT[1][8 + g];
        float2 eA = *(const float2*)(g_Bt + (size_t)w1g  * KTAGS + n0);
        float2 eB = *(const float2*)(g_Bt + (size_t)w1g8 * KTAGS + n0);
        d0 = rb0 * eA.x; d1 = rb1 * eA.y;
        d2 = rb0 * eB.x; d3 = rb1 * eB.y;
    }

    // prefetch emissions for step t=2
    float2 eg, eg8;
    {
        int w2g  = sWT[2][g];
        int w2g8 = sWT[2][8 + g];
        eg  = *(const float2*)(g_Bt + (size_t)w2g  * KTAGS + n0);
        eg8 = *(const float2*)(g_Bt + (size_t)w2g8 * KTAGS + n0);
    }

    int p = 0;
    for (int t = 2; t <= TLEN - 2; ++t) {
        // publish own slice of alpha_{t-1} (bf16): x = row g, y = row g+8
        uint2 my;
        my.x = cvt_bf16x2(d1, d0);
        my.y = cvt_bf16x2(d3, d2);
        sX[p][w >> 1][lane][w & 1] = my;
        __syncthreads();

        // gather Af fragments: one LDS.128 per kc
        uint32_t Af[4][4];
#pragma unroll
        for (int kc = 0; kc < 4; kc++) {
            uint4 v = *(const uint4*)&sX[p][kc][lane][0];
            Af[kc][0] = v.x; Af[kc][1] = v.y; Af[kc][2] = v.z; Af[kc][3] = v.w;
        }

        // two independent depth-2 MMA chains
        float a0 = 0.f, a1 = 0.f, a2 = 0.f, a3 = 0.f;
        float b0 = 0.f, b1 = 0.f, b2 = 0.f, b3 = 0.f;
        mma16816(a0, a1, a2, a3, Af[0][0], Af[0][1], Af[0][2], Af[0][3], Bf[0][0], Bf[0][1]);
        mma16816(b0, b1, b2, b3, Af[2][0], Af[2][1], Af[2][2], Af[2][3], Bf[2][0], Bf[2][1]);
        mma16816(a0, a1, a2, a3, Af[1][0], Af[1][1], Af[1][2], Af[1][3], Bf[1][0], Bf[1][1]);
        mma16816(b0, b1, b2, b3, Af[3][0], Af[3][1], Af[3][2], Af[3][3], Bf[3][0], Bf[3][1]);

        // prefetch emissions for t+1 (issued after MMAs; t=254 reads pos 255: valid, unused)
        float2 ng, ng8;
        {
            int wn  = sWT[t + 1][g];
            int wn8 = sWT[t + 1][8 + g];
            ng  = *(const float2*)(g_Bt + (size_t)wn  * KTAGS + n0);
            ng8 = *(const float2*)(g_Bt + (size_t)wn8 * KTAGS + n0);
        }

        // fold chains + emission multiply (fp32)
        d0 = (a0 + b0) * eg.x;
        d1 = (a1 + b1) * eg.y;
        d2 = (a2 + b2) * eg8.x;
        d3 = (a3 + b3) * eg8.y;
        eg = ng; eg8 = ng8;
        p ^= 1;
    }

    // final transition into EOS: partial over own 2 tags, reduce q-group, warps
    {
        float zg  = d0 * eos0 + d1 * eos1;
        float zg8 = d2 * eos0 + d3 * eos1;
        zg  += __shfl_xor_sync(0xffffffffu, zg, 1);
        zg  += __shfl_xor_sync(0xffffffffu, zg, 2);
        zg8 += __shfl_xor_sync(0xffffffffu, zg8, 1);
        zg8 += __shfl_xor_sync(0xffffffffu, zg8, 2);
        if (q == 0) {
            sZ[w][g]     = zg;
            sZ[w][8 + g] = zg8;
        }
    }
    __syncthreads();
    if (tid < 16) {
        float z = 0.0f;
#pragma unroll
        for (int ww = 0; ww < 8; ww++) z += sZ[ww][tid];
        // + 255 * log(64) = 1530 * ln2 (fixed-scaling compensation)
        out[s0 + tid] = logf(z) + 1060.5151862567153f;
    }
}

// ---------------------------------------------------------------------------
extern "C" void kernel_launch(void* const* d_in, const int* in_sizes, int n_in,
                              void* d_out, int out_size) {
    const int*   words  = nullptr;
    const float* ThetaB = nullptr;
    const float* WA     = nullptr;
    const float* E      = nullptr;
    for (int i = 0; i < n_in; i++) {
        switch (in_sizes[i]) {
            case BATCHN * TLEN:   words  = (const int*)d_in[i];   break;
            case KTAGS * DDIM:    ThetaB = (const float*)d_in[i]; break;
            case KTAGS * KTAGS:   WA     = (const float*)d_in[i]; break;
            case NV * DDIM:       E      = (const float*)d_in[i]; break;
        }
    }
    float* out = (float*)d_out;

    emit_table_kernel<<<(NV + 63) / 64, 256>>>(ThetaB, E);
    crf_scan_kernel<<<BATCHN / 16, 256>>>(WA, words, out);
}